// round 14
// baseline (speedup 1.0000x reference)
#include <cuda_runtime.h>
#include <cuda_bf16.h>

#define Bn 32
#define Ln 512
#define Hn 256
#define NHn 4
#define DHn 64
#define LOG2E 1.4426950408889634f

// ---------------- scratch (device globals; no allocation) ----------------
__device__ __align__(16) unsigned g_xbf[Bn * Ln * 128];         // x bf16 pairs
__device__ __align__(16) unsigned g_wbf[5 * Hn * 128];          // Wq,Wk,Wv,Wtq,Wd bf16 pairs
__device__ __align__(16) unsigned g_q16[Bn * Ln * 128];         // q bf16 pairs
__device__ __align__(16) unsigned g_k16[Bn * Ln * 128];         // k bf16 pairs
__device__ __align__(16) __nv_bfloat16 g_vt16[Bn * NHn * DHn * Ln]; // V^T [b,h][d][token]
__device__ __align__(16) unsigned g_tq16[Bn * Ln * 128];        // tq bf16 pairs
__device__ __align__(16) unsigned g_gm[Bn * Ln * Ln];           // bf16x2 {gate/8*log2e, mask*log2e}
__device__ __align__(16) unsigned g_ctx16[Bn * Ln * 128];       // ctx bf16 pairs
__device__ __align__(16) unsigned g_tp1[Ln * Ln];               // bf16x2 {tw1, tb1}
__device__ __align__(16) unsigned g_tp2[Ln * Ln];               // bf16x2 {tow1, tow2}

// ---------------- helpers --------------------------------------------
__device__ __forceinline__ float tanh_ap(float x) {
    float y;
    asm("tanh.approx.f32 %0, %1;" : "=f"(y) : "f"(x));
    return y;
}
__device__ __forceinline__ unsigned packbf(float lo, float hi) {
    __nv_bfloat162 p = __floats2bfloat162_rn(lo, hi);
    return *(unsigned*)&p;
}
__device__ __forceinline__ void cpa16(void* s, const void* g) {
    unsigned sa = (unsigned)__cvta_generic_to_shared(s);
    asm volatile("cp.async.cg.shared.global [%0], [%1], 16;" :: "r"(sa), "l"(g));
}
#define CP_COMMIT()  asm volatile("cp.async.commit_group;")
#define CP_WAIT1()   asm volatile("cp.async.wait_group 1;")
#define CP_WAIT0()   asm volatile("cp.async.wait_group 0;")

__device__ __forceinline__ void mma_bf16(float* c, const unsigned* a, const unsigned* b) {
    asm volatile(
        "mma.sync.aligned.m16n8k16.row.col.f32.bf16.bf16.f32 "
        "{%0,%1,%2,%3}, {%4,%5,%6,%7}, {%8,%9}, {%0,%1,%2,%3};\n"
        : "+f"(c[0]), "+f"(c[1]), "+f"(c[2]), "+f"(c[3])
        : "r"(a[0]), "r"(a[1]), "r"(a[2]), "r"(a[3]), "r"(b[0]), "r"(b[1]));
}

// 64x64x256 bf16 GEMM mainloop, cp.async double buffered.
__device__ __forceinline__ void gemm_bf16(
    const unsigned* __restrict__ Ag, const unsigned* __restrict__ Bg,
    int m0, int n0, int t, int wm, int gid, int tig,
    unsigned (*As)[64][36], unsigned (*Bs)[64][36], float c[8][4])
{
#pragma unroll
    for (int u = 0; u < 4; ++u) {
        int f = t + 128 * u;
        int row = f >> 3;
        int ch = (f & 7) * 4;
        cpa16(&As[0][row][ch], &Ag[(size_t)(m0 + row) * 128 + ch]);
        cpa16(&Bs[0][row][ch], &Bg[(size_t)(n0 + row) * 128 + ch]);
    }
    CP_COMMIT();

    for (int i = 0; i < 4; ++i) {
        const int buf = i & 1;
        if (i < 3) {
            const int p1 = (i + 1) * 32;
            const int nb = buf ^ 1;
#pragma unroll
            for (int u = 0; u < 4; ++u) {
                int f = t + 128 * u;
                int row = f >> 3;
                int ch = (f & 7) * 4;
                cpa16(&As[nb][row][ch], &Ag[(size_t)(m0 + row) * 128 + p1 + ch]);
                cpa16(&Bs[nb][row][ch], &Bg[(size_t)(n0 + row) * 128 + p1 + ch]);
            }
            CP_COMMIT();
            CP_WAIT1();
        } else {
            CP_WAIT0();
        }
        __syncthreads();
#pragma unroll
        for (int ks = 0; ks < 4; ++ks) {
            unsigned a[4];
            a[0] = As[buf][wm + gid][ks * 8 + tig];
            a[1] = As[buf][wm + gid + 8][ks * 8 + tig];
            a[2] = As[buf][wm + gid][ks * 8 + 4 + tig];
            a[3] = As[buf][wm + gid + 8][ks * 8 + 4 + tig];
#pragma unroll
            for (int nt = 0; nt < 8; ++nt) {
                unsigned b[2];
                b[0] = Bs[buf][nt * 8 + gid][ks * 8 + tig];
                b[1] = Bs[buf][nt * 8 + gid][ks * 8 + 4 + tig];
                mma_bf16(c[nt], a, b);
            }
        }
        __syncthreads();
    }
}

// ---------------- K-1: fused pre-convert (x, weights, time params) --------
#define XN4 (Bn * Ln * Hn / 4)     // 1048576 float4s
#define WN4 (5 * Hn * Hn / 4)      // 81920
#define T4  (Ln * Ln / 4)          // 65536
#define NCVT (XN4 + WN4 + 2 * T4)  // 1261568
__global__ __launch_bounds__(256) void cvt_all(
    const float4* __restrict__ x,
    const float4* __restrict__ Wq, const float4* __restrict__ Wk,
    const float4* __restrict__ Wv, const float4* __restrict__ Wtq,
    const float4* __restrict__ Wd,
    const float4* __restrict__ tw1, const float4* __restrict__ tb1,
    const float4* __restrict__ tow1, const float4* __restrict__ tow2)
{
    int i = blockIdx.x * 256 + threadIdx.x;
    if (i < XN4) {
        float4 v = x[i];
        ((uint2*)g_xbf)[i] = make_uint2(packbf(v.x, v.y), packbf(v.z, v.w));
    } else if (i < XN4 + WN4) {
        int j = i - XN4;
        int m = j >> 14, r = j & 16383;
        const float4* src = m == 0 ? Wq : m == 1 ? Wk : m == 2 ? Wv : m == 3 ? Wtq : Wd;
        float4 v = src[r];
        ((uint2*)g_wbf)[j] = make_uint2(packbf(v.x, v.y), packbf(v.z, v.w));
    } else if (i < XN4 + WN4 + T4) {
        int j = i - XN4 - WN4;
        float4 w = tw1[j], b = tb1[j];
        ((uint4*)g_tp1)[j] = make_uint4(packbf(w.x, b.x), packbf(w.y, b.y),
                                        packbf(w.z, b.z), packbf(w.w, b.w));
    } else if (i < NCVT) {
        int j = i - XN4 - WN4 - T4;
        float4 w = tow1[j], b = tow2[j];
        ((uint4*)g_tp2)[j] = make_uint4(packbf(w.x, b.x), packbf(w.y, b.y),
                                        packbf(w.z, b.z), packbf(w.w, b.w));
    }
}

// ---------------- K0a: TQ projection (critical path for gate) -------------
__global__ __launch_bounds__(128) void proj_tq(const float* __restrict__ btq)
{
    __shared__ unsigned As[2][64][36];
    __shared__ unsigned Bs[2][64][36];
    const int t = threadIdx.x;
    const int lane = t & 31, warp = t >> 5;
    const int gid = lane >> 2, tig = lane & 3;
    const int m0 = blockIdx.x * 64;
    const int n0 = blockIdx.y * 64;
    const int wm = warp * 16;

    float c[8][4] = {};
    gemm_bf16(g_xbf, g_wbf + 3 * Hn * 128, m0, n0, t, wm, gid, tig, As, Bs, c);

    const int r0 = m0 + wm + gid, r1 = r0 + 8;
#pragma unroll
    for (int nt = 0; nt < 8; ++nt) {
        int cc = n0 + nt * 8 + 2 * tig;
        float2 bb = *(const float2*)&btq[cc];
        g_tq16[(size_t)r0 * 128 + (cc >> 1)] = packbf(c[nt][0] + bb.x, c[nt][1] + bb.y);
        g_tq16[(size_t)r1 * 128 + (cc >> 1)] = packbf(c[nt][2] + bb.x, c[nt][3] + bb.y);
    }
}

// ---------------- K0b: fused gate + Q/K/V projection ----------------------
#define GATE_BLKS 2048
__global__ __launch_bounds__(128) void fused_gate_qkv(
    const float* __restrict__ tseq, const float* __restrict__ tob,
    const float* __restrict__ mask,
    const float* __restrict__ bq, const float* __restrict__ bk,
    const float* __restrict__ bv)
{
    __shared__ unsigned As[2][64][36];
    __shared__ unsigned Bs[2][64][36];
    const int t = threadIdx.x;
    const int lane = t & 31, warp = t >> 5;
    const int gid = lane >> 2, tig = lane & 3;
    const int wm = warp * 16;
    const int bid = blockIdx.x;

    float c[8][4] = {};

    if (bid < GATE_BLKS) {
        // ---------------- gate path ----------------
        const int b = bid >> 6;
        const int rem = bid & 63;
        const int m0 = (rem >> 3) * 64;
        const int n0 = (rem & 7) * 64;
        gemm_bf16(g_tq16 + (size_t)b * Ln * 128, g_xbf + (size_t)b * Ln * 128,
                  m0, n0, t, wm, gid, tig, As, Bs, c);

        const int rl = m0 + wm + gid, rh = rl + 8;
        const float t_lo = tseq[b * Ln + rl];
        const float t_hi = tseq[b * Ln + rh];
        const float* mptr = mask + (size_t)b * Ln * Ln;
        unsigned* gout = g_gm + (size_t)b * Ln * Ln;

#pragma unroll
        for (int nt = 0; nt < 8; ++nt) {
            int cc = n0 + nt * 8 + 2 * tig;
            float2 tc = *(const float2*)&tseq[b * Ln + cc];
#pragma unroll
            for (int half = 0; half < 2; ++half) {
                int r = half ? rh : rl;
                float tr = half ? t_hi : t_lo;
                size_t pidx = (size_t)r * Ln + cc;
                uint2 P1 = *(const uint2*)&g_tp1[pidx];
                uint2 P2 = *(const uint2*)&g_tp2[pidx];
                float2 wb0 = __bfloat1622float2(*(__nv_bfloat162*)&P1.x);  // {tw1,tb1}
                float2 wb1 = __bfloat1622float2(*(__nv_bfloat162*)&P1.y);
                float2 ow0 = __bfloat1622float2(*(__nv_bfloat162*)&P2.x);  // {tow1,tow2}
                float2 ow1 = __bfloat1622float2(*(__nv_bfloat162*)&P2.y);
                float2 ob = *(const float2*)&tob[pidx];
                float2 mm = *(const float2*)&mptr[pidx];
                float s0 = c[nt][half * 2 + 0], s1 = c[nt][half * 2 + 1];
                float tqk0 = tanh_ap(s0), tqk1 = tanh_ap(s1);
                float d0 = tanh_ap(__logf(1.0f + fabsf(tr - tc.x)) * wb0.x + wb0.y);
                float d1 = tanh_ap(__logf(1.0f + fabsf(tr - tc.y)) * wb1.x + wb1.y);
                float g0 = ow0.x * d0 + ow0.y * tqk0 + ob.x;
                float g1 = ow1.x * d1 + ow1.y * tqk1 + ob.y;
                // pre-scale by log2e: attn uses exp2 directly
                g0 = (0.125f * LOG2E) / (1.0f + __expf(-g0));
                g1 = (0.125f * LOG2E) / (1.0f + __expf(-g1));
                __nv_bfloat162 p0 = __floats2bfloat162_rn(g0, mm.x * LOG2E);
                __nv_bfloat162 p1 = __floats2bfloat162_rn(g1, mm.y * LOG2E);
                *(uint2*)&gout[pidx] = make_uint2(*(unsigned*)&p0, *(unsigned*)&p1);
            }
        }
    } else {
        // ---------------- Q/K/V projection path ----------------
        const int pid = bid - GATE_BLKS;
        const int mt = pid / 12, combo = pid % 12;
        const int wsel = combo >> 2;
        const int m0 = mt * 64;
        const int n0 = (combo & 3) * 64;
        const float* bias = wsel == 0 ? bq : wsel == 1 ? bk : bv;

        gemm_bf16(g_xbf, g_wbf + (size_t)wsel * Hn * 128,
                  m0, n0, t, wm, gid, tig, As, Bs, c);

        const int r0 = m0 + wm + gid, r1 = r0 + 8;
        if (wsel < 2) {
            unsigned* out16 = wsel == 0 ? g_q16 : g_k16;
#pragma unroll
            for (int nt = 0; nt < 8; ++nt) {
                int cc = n0 + nt * 8 + 2 * tig;
                float2 bb = *(const float2*)&bias[cc];
                out16[(size_t)r0 * 128 + (cc >> 1)] = packbf(c[nt][0] + bb.x, c[nt][1] + bb.y);
                out16[(size_t)r1 * 128 + (cc >> 1)] = packbf(c[nt][2] + bb.x, c[nt][3] + bb.y);
            }
        } else {
            const int bb0 = r0 >> 9;
            const int tk0 = r0 & 511;
#pragma unroll
            for (int nt = 0; nt < 8; ++nt) {
                int cc = n0 + nt * 8 + 2 * tig;
                float2 bbv = *(const float2*)&bias[cc];
                int hh = cc >> 6, dl = cc & 63;
                size_t base = ((size_t)(bb0 * NHn + hh) * DHn + dl) * Ln + tk0;
                g_vt16[base]           = __float2bfloat16(c[nt][0] + bbv.x);
                g_vt16[base + Ln]      = __float2bfloat16(c[nt][1] + bbv.y);
                g_vt16[base + 8]       = __float2bfloat16(c[nt][2] + bbv.x);
                g_vt16[base + Ln + 8]  = __float2bfloat16(c[nt][3] + bbv.y);
            }
        }
    }
}

// ---------------- K2: fused attention (bf16, no-max softmax, exp2) --------
__global__ __launch_bounds__(128) void attn_mma()
{
    __shared__ unsigned Qs[64][36];
    __shared__ unsigned Ks[2][64][36];
    __shared__ unsigned Vp[2][64][36];
    __shared__ unsigned Gm[64][68];

    const int t = threadIdx.x;
    const int lane = t & 31, warp = t >> 5;
    const int gid = lane >> 2, tig = lane & 3;
    const int qt = blockIdx.x, h = blockIdx.y, b = blockIdx.z;
    const int q0 = qt * 64;
    const int wm = warp * 16;

    const unsigned* qptr = g_q16 + (size_t)b * Ln * 128 + h * 32;
    const unsigned* kptr = g_k16 + (size_t)b * Ln * 128 + h * 32;
    const unsigned* vtp = (const unsigned*)(g_vt16 + ((size_t)(b * NHn + h)) * DHn * Ln);
    const unsigned* gptr = g_gm + (size_t)b * Ln * Ln;

#pragma unroll
    for (int u = 0; u < 4; ++u) {
        int f = t + 128 * u;
        int row = f >> 3;
        int ch = (f & 7) * 4;
        *(uint4*)&Qs[row][ch] = *(const uint4*)&qptr[(size_t)(q0 + row) * 128 + ch];
    }

#pragma unroll
    for (int u = 0; u < 4; ++u) {
        int f = t + 128 * u;
        int row = f >> 3;
        int ch = (f & 7) * 4;
        cpa16(&Ks[0][row][ch], &kptr[(size_t)row * 128 + ch]);
        cpa16(&Vp[0][row][ch], &vtp[(size_t)row * 256 + ch]);
    }
    CP_COMMIT();
    __syncthreads();

    unsigned qf[4][4];
#pragma unroll
    for (int ks = 0; ks < 4; ++ks) {
        qf[ks][0] = Qs[wm + gid][ks * 8 + tig];
        qf[ks][1] = Qs[wm + gid + 8][ks * 8 + tig];
        qf[ks][2] = Qs[wm + gid][ks * 8 + 4 + tig];
        qf[ks][3] = Qs[wm + gid + 8][ks * 8 + 4 + tig];
    }

    float o[8][4] = {};
    float l_lo = 0.f, l_hi = 0.f;
    const int rl = q0 + wm + gid, rh = rl + 8;
    const int lrl = wm + gid, lrh = lrl + 8;

    for (int kb = 0; kb < 8; ++kb) {
        const int c0 = kb * 64;
        const int buf = kb & 1;

#pragma unroll
        for (int u = 0; u < 8; ++u) {
            int f = t + 128 * u;
            int row = f >> 4;
            int seg = (f & 15) * 4;
            cpa16(&Gm[row][seg], &gptr[(size_t)(q0 + row) * Ln + c0 + seg]);
        }
        CP_COMMIT();

        if (kb < 7) {
            const int c1 = c0 + 64;
            const int nb = buf ^ 1;
#pragma unroll
            for (int u = 0; u < 4; ++u) {
                int f = t + 128 * u;
                int row = f >> 3;
                int ch = (f & 7) * 4;
                cpa16(&Ks[nb][row][ch], &kptr[(size_t)(c1 + row) * 128 + ch]);
                cpa16(&Vp[nb][row][ch], &vtp[(size_t)row * 256 + (c1 >> 1) + ch]);
            }
            CP_COMMIT();
            CP_WAIT1();
        } else {
            CP_WAIT0();
        }
        __syncthreads();

        // S = Q @ K^T
        float s[8][4] = {};
#pragma unroll
        for (int ks = 0; ks < 4; ++ks) {
#pragma unroll
            for (int nt = 0; nt < 8; ++nt) {
                unsigned bfr[2];
                bfr[0] = Ks[buf][nt * 8 + gid][ks * 8 + tig];
                bfr[1] = Ks[buf][nt * 8 + gid][ks * 8 + 4 + tig];
                mma_bf16(s[nt], qf[ks], bfr);
            }
        }

        // p = exp2(s*gate' + mask')   (gate', mask' pre-scaled by log2e; no max needed)
        float rs_lo = 0.f, rs_hi = 0.f;
#pragma unroll
        for (int nt = 0; nt < 8; ++nt) {
            int cl = nt * 8 + 2 * tig;
            uint2 pl = *(const uint2*)&Gm[lrl][cl];
            uint2 ph = *(const uint2*)&Gm[lrh][cl];
            float2 e0 = __bfloat1622float2(*(__nv_bfloat162*)&pl.x);
            float2 e1 = __bfloat1622float2(*(__nv_bfloat162*)&pl.y);
            float2 e2 = __bfloat1622float2(*(__nv_bfloat162*)&ph.x);
            float2 e3 = __bfloat1622float2(*(__nv_bfloat162*)&ph.y);
            s[nt][0] = exp2f(s[nt][0] * e0.x + e0.y);
            s[nt][1] = exp2f(s[nt][1] * e1.x + e1.y);
            s[nt][2] = exp2f(s[nt][2] * e2.x + e2.y);
            s[nt][3] = exp2f(s[nt][3] * e3.x + e3.y);
            rs_lo += s[nt][0] + s[nt][1];
            rs_hi += s[nt][2] + s[nt][3];
        }
        rs_lo += __shfl_xor_sync(0xffffffffu, rs_lo, 1);
        rs_lo += __shfl_xor_sync(0xffffffffu, rs_lo, 2);
        rs_hi += __shfl_xor_sync(0xffffffffu, rs_hi, 1);
        rs_hi += __shfl_xor_sync(0xffffffffu, rs_hi, 2);
        l_lo += rs_lo;
        l_hi += rs_hi;

        // O += P @ V
#pragma unroll
        for (int ks = 0; ks < 4; ++ks) {
            unsigned pa[4];
            pa[0] = packbf(s[2 * ks][0], s[2 * ks][1]);
            pa[1] = packbf(s[2 * ks][2], s[2 * ks][3]);
            pa[2] = packbf(s[2 * ks + 1][0], s[2 * ks + 1][1]);
            pa[3] = packbf(s[2 * ks + 1][2], s[2 * ks + 1][3]);
#pragma unroll
            for (int dt = 0; dt < 8; ++dt) {
                unsigned bfr[2];
                bfr[0] = Vp[buf][dt * 8 + gid][ks * 8 + tig];
                bfr[1] = Vp[buf][dt * 8 + gid][ks * 8 + 4 + tig];
                mma_bf16(o[dt], pa, bfr);
            }
        }
        __syncthreads();
    }

    float inv_lo = 1.0f / l_lo, inv_hi = 1.0f / l_hi;
    unsigned* cbase = g_ctx16 + (size_t)b * Ln * 128;
#pragma unroll
    for (int dt = 0; dt < 8; ++dt) {
        int pcol = h * 32 + dt * 4 + tig;
        cbase[(size_t)rl * 128 + pcol] = packbf(o[dt][0] * inv_lo, o[dt][1] * inv_lo);
        cbase[(size_t)rh * 128 + pcol] = packbf(o[dt][2] * inv_hi, o[dt][3] * inv_hi);
    }
}

// ---------------- K3: output projection + residual + layernorm ------------
__global__ __launch_bounds__(512) void outln_mma(
    const float* __restrict__ x, const float* __restrict__ bd,
    const float* __restrict__ lng, const float* __restrict__ lnb,
    float* __restrict__ out)
{
    extern __shared__ unsigned dsm[];
    unsigned* As = dsm;             // 2 * 64 * 36  = 4608
    unsigned* Bs = dsm + 4608;      // 2 * 256 * 36 = 18432
    __shared__ float redS[64][4];
    __shared__ float redQ[64][4];

    const int t = threadIdx.x;
    const int lane = t & 31, warp = t >> 5;
    const int gid = lane >> 2, tig = lane & 3;
    const int m0 = blockIdx.x * 64;
    const int mg = warp >> 2;
    const int nq = warp & 3;
    const int wm = mg * 16;
    const int wn = nq * 64;
    const unsigned* Wd = g_wbf + 4 * Hn * 128;

    float c[8][4] = {};

    {
        int row = t >> 3, ch = (t & 7) * 4;
        cpa16(&As[row * 36 + ch], &g_ctx16[(size_t)(m0 + row) * 128 + ch]);
#pragma unroll
        for (int u = 0; u < 4; ++u) {
            int f = t + 512 * u;
            int r2 = f >> 3, c2 = (f & 7) * 4;
            cpa16(&Bs[r2 * 36 + c2], &Wd[(size_t)r2 * 128 + c2]);
        }
        CP_COMMIT();
    }

    for (int i = 0; i < 4; ++i) {
        const int buf = i & 1;
        if (i < 3) {
            const int p1 = (i + 1) * 32;
            const int nb = buf ^ 1;
            int row = t >> 3, ch = (t & 7) * 4;
            cpa16(&As[nb * 2304 + row * 36 + ch], &g_ctx16[(size_t)(m0 + row) * 128 + p1 + ch]);
#pragma unroll
            for (int u = 0; u < 4; ++u) {
                int f = t + 512 * u;
                int r2 = f >> 3, c2 = (f & 7) * 4;
                cpa16(&Bs[nb * 9216 + r2 * 36 + c2], &Wd[(size_t)r2 * 128 + p1 + c2]);
            }
            CP_COMMIT();
            CP_WAIT1();
        } else {
            CP_WAIT0();
        }
        __syncthreads();
#pragma unroll
        for (int ks = 0; ks < 4; ++ks) {
            unsigned a[4];
            a[0] = As[buf * 2304 + (wm + gid) * 36 + ks * 8 + tig];
            a[1] = As[buf * 2304 + (wm + gid + 8) * 36 + ks * 8 + tig];
            a[2] = As[buf * 2304 + (wm + gid) * 36 + ks * 8 + 4 + tig];
            a[3] = As[buf * 2304 + (wm + gid + 8) * 36 + ks * 8 + 4 + tig];
#pragma unroll
            for (int nt = 0; nt < 8; ++nt) {
                unsigned bfr[2];
                bfr[0] = Bs[buf * 9216 + (wn + nt * 8 + gid) * 36 + ks * 8 + tig];
                bfr[1] = Bs[buf * 9216 + (wn + nt * 8 + gid) * 36 + ks * 8 + 4 + tig];
                mma_bf16(c[nt], a, bfr);
            }
        }
        __syncthreads();
    }

    const int lrl = wm + gid, lrh = lrl + 8;
    const size_t rl = m0 + lrl, rh = m0 + lrh;
    float s_lo = 0.f, s_hi = 0.f, q_lo = 0.f, q_hi = 0.f;
#pragma unroll
    for (int nt = 0; nt < 8; ++nt) {
        int cc = wn + nt * 8 + 2 * tig;
        float2 bb = *(const float2*)&bd[cc];
        float2 xl = *(const float2*)&x[rl * Hn + cc];
        float2 xh = *(const float2*)&x[rh * Hn + cc];
        c[nt][0] += bb.x + xl.x; c[nt][1] += bb.y + xl.y;
        c[nt][2] += bb.x + xh.x; c[nt][3] += bb.y + xh.y;
        s_lo += c[nt][0] + c[nt][1];
        s_hi += c[nt][2] + c[nt][3];
        q_lo += c[nt][0] * c[nt][0] + c[nt][1] * c[nt][1];
        q_hi += c[nt][2] * c[nt][2] + c[nt][3] * c[nt][3];
    }
    s_lo += __shfl_xor_sync(0xffffffffu, s_lo, 1);
    s_lo += __shfl_xor_sync(0xffffffffu, s_lo, 2);
    s_hi += __shfl_xor_sync(0xffffffffu, s_hi, 1);
    s_hi += __shfl_xor_sync(0xffffffffu, s_hi, 2);
    q_lo += __shfl_xor_sync(0xffffffffu, q_lo, 1);
    q_lo += __shfl_xor_sync(0xffffffffu, q_lo, 2);
    q_hi += __shfl_xor_sync(0xffffffffu, q_hi, 1);
    q_hi += __shfl_xor_sync(0xffffffffu, q_hi, 2);
    __syncthreads();
    if (tig == 0) {
        redS[lrl][nq] = s_lo; redQ[lrl][nq] = q_lo;
        redS[lrh][nq] = s_hi; redQ[lrh][nq] = q_hi;
    }
    __syncthreads();
    float mu_lo = (redS[lrl][0] + redS[lrl][1] + redS[lrl][2] + redS[lrl][3]) * (1.0f / Hn);
    float mu_hi = (redS[lrh][0] + redS[lrh][1] + redS[lrh][2] + redS[lrh][3]) * (1.0f / Hn);
    float ex_lo = (redQ[lrl][0] + redQ[lrl][1] + redQ[lrl][2] + redQ[lrl][3]) * (1.0f / Hn);
    float ex_hi = (redQ[lrh][0] + redQ[lrh][1] + redQ[lrh][2] + redQ[lrh][3]) * (1.0f / Hn);
    float iv_lo = rsqrtf(ex_lo - mu_lo * mu_lo + 1e-12f);
    float iv_hi = rsqrtf(ex_hi - mu_hi * mu_hi + 1e-12f);

#pragma unroll
    for (int nt = 0; nt < 8; ++nt) {
        int cc = wn + nt * 8 + 2 * tig;
        float2 g = *(const float2*)&lng[cc];
        float2 be = *(const float2*)&lnb[cc];
        *(float2*)&out[rl * Hn + cc] = make_float2(
            (c[nt][0] - mu_lo) * iv_lo * g.x + be.x,
            (c[nt][1] - mu_lo) * iv_lo * g.y + be.y);
        *(float2*)&out[rh * Hn + cc] = make_float2(
            (c[nt][2] - mu_hi) * iv_hi * g.x + be.x,
            (c[nt][3] - mu_hi) * iv_hi * g.y + be.y);
    }
}

// ---------------- K4: interval prediction head ---------------------------
__global__ __launch_bounds__(256) void pred_kernel(
    const float* __restrict__ hs, const int* __restrict__ slen,
    const float* __restrict__ Wt, const float* __restrict__ bt,
    float* __restrict__ out)
{
    __shared__ float red[256];
    const int b = blockIdx.x;
    const int t = threadIdx.x;
    const int len = slen[b];
    const float* e1 = hs + ((size_t)b * Ln + (len - 1)) * Hn;
    const float* e2 = hs + ((size_t)b * Ln + (len - 2)) * Hn;
    red[t] = Wt[t] * e1[t] + Wt[Hn + t] * e2[t];
    __syncthreads();
    for (int s = 128; s > 0; s >>= 1) {
        if (t < s) red[t] += red[t + s];
        __syncthreads();
    }
    if (t == 0) out[(size_t)Bn * Ln * Hn + b] = red[0] + bt[0];
}

// ---------------- launch --------------------------------------------------
extern "C" void kernel_launch(void* const* d_in, const int* in_sizes, int n_in,
                              void* d_out, int out_size)
{
    const float* x    = (const float*)d_in[0];
    const float* tseq = (const float*)d_in[1];
    const float* mask = (const float*)d_in[2];
    const int*   slen = (const int*)d_in[3];
    const float* Wq   = (const float*)d_in[4];
    const float* bq   = (const float*)d_in[5];
    const float* Wk   = (const float*)d_in[6];
    const float* bk   = (const float*)d_in[7];
    const float* Wv   = (const float*)d_in[8];
    const float* bv   = (const float*)d_in[9];
    const float* Wd   = (const float*)d_in[10];
    const float* bd   = (const float*)d_in[11];
    const float* lng  = (const float*)d_in[12];
    const float* lnb  = (const float*)d_in[13];
    const float* Wtq  = (const float*)d_in[14];
    const float* btq  = (const float*)d_in[15];
    const float* tw1  = (const float*)d_in[16];
    const float* tb1  = (const float*)d_in[17];
    const float* tow1 = (const float*)d_in[18];
    const float* tow2 = (const float*)d_in[19];
    const float* tob  = (const float*)d_in[20];
    const float* Wt   = (const float*)d_in[21];
    const float* bt   = (const float*)d_in[22];
    float* out = (float*)d_out;

    static const int OUTLN_SMEM = (4608 + 18432) * 4;  // 92160 B dynamic
    cudaFuncSetAttribute(outln_mma, cudaFuncAttributeMaxDynamicSharedMemorySize, OUTLN_SMEM);

    cvt_all<<<(NCVT + 255) / 256, 256>>>(
        (const float4*)x, (const float4*)Wq, (const float4*)Wk,
        (const float4*)Wv, (const float4*)Wtq, (const float4*)Wd,
        (const float4*)tw1, (const float4*)tb1,
        (const float4*)tow1, (const float4*)tow2);
    proj_tq<<<dim3(Bn * Ln / 64, 4), 128>>>(btq);
    fused_gate_qkv<<<GATE_BLKS + 3072, 128>>>(tseq, tob, mask, bq, bk, bv);
    attn_mma<<<dim3(Ln / 64, NHn, Bn), 128>>>();
    outln_mma<<<dim3(Bn * Ln / 64), 512, OUTLN_SMEM>>>(x, bd, lng, lnb, out);
    pred_kernel<<<dim3(Bn), 256>>>(out, slen, Wt, bt, out);
}

// round 15
// speedup vs baseline: 1.4665x; 1.4665x over previous
#include <cuda_runtime.h>
#include <cuda_bf16.h>

#define Bn 32
#define Ln 512
#define Hn 256
#define NHn 4
#define DHn 64
#define LOG2E 1.4426950408889634f

// ---------------- scratch (device globals; no allocation) ----------------
__device__ __align__(16) unsigned g_xbf[Bn * Ln * 128];         // x bf16 pairs
__device__ __align__(16) unsigned g_wbf[5 * Hn * 128];          // Wq,Wk,Wv,Wtq,Wd bf16 pairs
__device__ __align__(16) unsigned g_q16[Bn * Ln * 128];         // q bf16 pairs
__device__ __align__(16) unsigned g_k16[Bn * Ln * 128];         // k bf16 pairs
__device__ __align__(16) __nv_bfloat16 g_vt16[Bn * NHn * DHn * Ln]; // V^T [b,h][d][token]
__device__ __align__(16) unsigned g_tq16[Bn * Ln * 128];        // tq bf16 pairs
__device__ __align__(16) unsigned g_gm[Bn * Ln * Ln];           // bf16x2 {gate/8*log2e, mask*log2e}
__device__ __align__(16) unsigned g_ctx16[Bn * Ln * 128];       // ctx bf16 pairs
__device__ __align__(16) unsigned g_tp1[Ln * Ln];               // bf16x2 {tw1, tb1}
__device__ __align__(16) unsigned g_tp2[Ln * Ln];               // bf16x2 {tow1, tow2}

// ---------------- helpers --------------------------------------------
__device__ __forceinline__ float tanh_ap(float x) {
    float y;
    asm("tanh.approx.f32 %0, %1;" : "=f"(y) : "f"(x));
    return y;
}
__device__ __forceinline__ float ex2_ap(float x) {
    float y;
    asm("ex2.approx.ftz.f32 %0, %1;" : "=f"(y) : "f"(x));
    return y;
}
__device__ __forceinline__ unsigned packbf(float lo, float hi) {
    __nv_bfloat162 p = __floats2bfloat162_rn(lo, hi);
    return *(unsigned*)&p;
}
__device__ __forceinline__ void cpa16(void* s, const void* g) {
    unsigned sa = (unsigned)__cvta_generic_to_shared(s);
    asm volatile("cp.async.cg.shared.global [%0], [%1], 16;" :: "r"(sa), "l"(g));
}
#define CP_COMMIT()  asm volatile("cp.async.commit_group;")
#define CP_WAIT1()   asm volatile("cp.async.wait_group 1;")
#define CP_WAIT0()   asm volatile("cp.async.wait_group 0;")

__device__ __forceinline__ void mma_bf16(float* c, const unsigned* a, const unsigned* b) {
    asm volatile(
        "mma.sync.aligned.m16n8k16.row.col.f32.bf16.bf16.f32 "
        "{%0,%1,%2,%3}, {%4,%5,%6,%7}, {%8,%9}, {%0,%1,%2,%3};\n"
        : "+f"(c[0]), "+f"(c[1]), "+f"(c[2]), "+f"(c[3])
        : "r"(a[0]), "r"(a[1]), "r"(a[2]), "r"(a[3]), "r"(b[0]), "r"(b[1]));
}

// 64x64x256 bf16 GEMM mainloop, cp.async double buffered.
__device__ __forceinline__ void gemm_bf16(
    const unsigned* __restrict__ Ag, const unsigned* __restrict__ Bg,
    int m0, int n0, int t, int wm, int gid, int tig,
    unsigned (*As)[64][36], unsigned (*Bs)[64][36], float c[8][4])
{
#pragma unroll
    for (int u = 0; u < 4; ++u) {
        int f = t + 128 * u;
        int row = f >> 3;
        int ch = (f & 7) * 4;
        cpa16(&As[0][row][ch], &Ag[(size_t)(m0 + row) * 128 + ch]);
        cpa16(&Bs[0][row][ch], &Bg[(size_t)(n0 + row) * 128 + ch]);
    }
    CP_COMMIT();

    for (int i = 0; i < 4; ++i) {
        const int buf = i & 1;
        if (i < 3) {
            const int p1 = (i + 1) * 32;
            const int nb = buf ^ 1;
#pragma unroll
            for (int u = 0; u < 4; ++u) {
                int f = t + 128 * u;
                int row = f >> 3;
                int ch = (f & 7) * 4;
                cpa16(&As[nb][row][ch], &Ag[(size_t)(m0 + row) * 128 + p1 + ch]);
                cpa16(&Bs[nb][row][ch], &Bg[(size_t)(n0 + row) * 128 + p1 + ch]);
            }
            CP_COMMIT();
            CP_WAIT1();
        } else {
            CP_WAIT0();
        }
        __syncthreads();
#pragma unroll
        for (int ks = 0; ks < 4; ++ks) {
            unsigned a[4];
            a[0] = As[buf][wm + gid][ks * 8 + tig];
            a[1] = As[buf][wm + gid + 8][ks * 8 + tig];
            a[2] = As[buf][wm + gid][ks * 8 + 4 + tig];
            a[3] = As[buf][wm + gid + 8][ks * 8 + 4 + tig];
#pragma unroll
            for (int nt = 0; nt < 8; ++nt) {
                unsigned b[2];
                b[0] = Bs[buf][nt * 8 + gid][ks * 8 + tig];
                b[1] = Bs[buf][nt * 8 + gid][ks * 8 + 4 + tig];
                mma_bf16(c[nt], a, b);
            }
        }
        __syncthreads();
    }
}

// ---------------- K-1: fused pre-convert (x, weights, time params) --------
#define XN4 (Bn * Ln * Hn / 4)     // 1048576 float4s
#define WN4 (5 * Hn * Hn / 4)      // 81920
#define T4  (Ln * Ln / 4)          // 65536
#define NCVT (XN4 + WN4 + 2 * T4)  // 1261568
__global__ __launch_bounds__(256) void cvt_all(
    const float4* __restrict__ x,
    const float4* __restrict__ Wq, const float4* __restrict__ Wk,
    const float4* __restrict__ Wv, const float4* __restrict__ Wtq,
    const float4* __restrict__ Wd,
    const float4* __restrict__ tw1, const float4* __restrict__ tb1,
    const float4* __restrict__ tow1, const float4* __restrict__ tow2)
{
    int i = blockIdx.x * 256 + threadIdx.x;
    if (i < XN4) {
        float4 v = x[i];
        ((uint2*)g_xbf)[i] = make_uint2(packbf(v.x, v.y), packbf(v.z, v.w));
    } else if (i < XN4 + WN4) {
        int j = i - XN4;
        int m = j >> 14, r = j & 16383;
        const float4* src = m == 0 ? Wq : m == 1 ? Wk : m == 2 ? Wv : m == 3 ? Wtq : Wd;
        float4 v = src[r];
        ((uint2*)g_wbf)[j] = make_uint2(packbf(v.x, v.y), packbf(v.z, v.w));
    } else if (i < XN4 + WN4 + T4) {
        int j = i - XN4 - WN4;
        float4 w = tw1[j], b = tb1[j];
        ((uint4*)g_tp1)[j] = make_uint4(packbf(w.x, b.x), packbf(w.y, b.y),
                                        packbf(w.z, b.z), packbf(w.w, b.w));
    } else if (i < NCVT) {
        int j = i - XN4 - WN4 - T4;
        float4 w = tow1[j], b = tow2[j];
        ((uint4*)g_tp2)[j] = make_uint4(packbf(w.x, b.x), packbf(w.y, b.y),
                                        packbf(w.z, b.z), packbf(w.w, b.w));
    }
}

// ---------------- K0a: TQ projection (critical path for gate) -------------
__global__ __launch_bounds__(128) void proj_tq(const float* __restrict__ btq)
{
    __shared__ unsigned As[2][64][36];
    __shared__ unsigned Bs[2][64][36];
    const int t = threadIdx.x;
    const int lane = t & 31, warp = t >> 5;
    const int gid = lane >> 2, tig = lane & 3;
    const int m0 = blockIdx.x * 64;
    const int n0 = blockIdx.y * 64;
    const int wm = warp * 16;

    float c[8][4] = {};
    gemm_bf16(g_xbf, g_wbf + 3 * Hn * 128, m0, n0, t, wm, gid, tig, As, Bs, c);

    const int r0 = m0 + wm + gid, r1 = r0 + 8;
#pragma unroll
    for (int nt = 0; nt < 8; ++nt) {
        int cc = n0 + nt * 8 + 2 * tig;
        float2 bb = *(const float2*)&btq[cc];
        g_tq16[(size_t)r0 * 128 + (cc >> 1)] = packbf(c[nt][0] + bb.x, c[nt][1] + bb.y);
        g_tq16[(size_t)r1 * 128 + (cc >> 1)] = packbf(c[nt][2] + bb.x, c[nt][3] + bb.y);
    }
}

// ---------------- K0b: fused gate + Q/K/V projection ----------------------
#define GATE_BLKS 2048
__global__ __launch_bounds__(128) void fused_gate_qkv(
    const float* __restrict__ tseq, const float* __restrict__ tob,
    const float* __restrict__ mask,
    const float* __restrict__ bq, const float* __restrict__ bk,
    const float* __restrict__ bv)
{
    __shared__ unsigned As[2][64][36];
    __shared__ unsigned Bs[2][64][36];
    const int t = threadIdx.x;
    const int lane = t & 31, warp = t >> 5;
    const int gid = lane >> 2, tig = lane & 3;
    const int wm = warp * 16;
    const int bid = blockIdx.x;

    float c[8][4] = {};

    if (bid < GATE_BLKS) {
        // ---------------- gate path ----------------
        const int b = bid >> 6;
        const int rem = bid & 63;
        const int m0 = (rem >> 3) * 64;
        const int n0 = (rem & 7) * 64;
        gemm_bf16(g_tq16 + (size_t)b * Ln * 128, g_xbf + (size_t)b * Ln * 128,
                  m0, n0, t, wm, gid, tig, As, Bs, c);

        const int rl = m0 + wm + gid, rh = rl + 8;
        const float t_lo = tseq[b * Ln + rl];
        const float t_hi = tseq[b * Ln + rh];
        const float* mptr = mask + (size_t)b * Ln * Ln;
        unsigned* gout = g_gm + (size_t)b * Ln * Ln;

#pragma unroll
        for (int nt = 0; nt < 8; ++nt) {
            int cc = n0 + nt * 8 + 2 * tig;
            float2 tc = *(const float2*)&tseq[b * Ln + cc];
#pragma unroll
            for (int half = 0; half < 2; ++half) {
                int r = half ? rh : rl;
                float tr = half ? t_hi : t_lo;
                size_t pidx = (size_t)r * Ln + cc;
                uint2 P1 = *(const uint2*)&g_tp1[pidx];
                uint2 P2 = *(const uint2*)&g_tp2[pidx];
                float2 wb0 = __bfloat1622float2(*(__nv_bfloat162*)&P1.x);  // {tw1,tb1}
                float2 wb1 = __bfloat1622float2(*(__nv_bfloat162*)&P1.y);
                float2 ow0 = __bfloat1622float2(*(__nv_bfloat162*)&P2.x);  // {tow1,tow2}
                float2 ow1 = __bfloat1622float2(*(__nv_bfloat162*)&P2.y);
                float2 ob = *(const float2*)&tob[pidx];
                float2 mm = *(const float2*)&mptr[pidx];
                float s0 = c[nt][half * 2 + 0], s1 = c[nt][half * 2 + 1];
                float tqk0 = tanh_ap(s0), tqk1 = tanh_ap(s1);
                float d0 = tanh_ap(__logf(1.0f + fabsf(tr - tc.x)) * wb0.x + wb0.y);
                float d1 = tanh_ap(__logf(1.0f + fabsf(tr - tc.y)) * wb1.x + wb1.y);
                float g0 = ow0.x * d0 + ow0.y * tqk0 + ob.x;
                float g1 = ow1.x * d1 + ow1.y * tqk1 + ob.y;
                // sigmoid via ex2: 1/(1+exp(-g)) = 1/(1+ex2(-g*log2e))
                g0 = (0.125f * LOG2E) / (1.0f + ex2_ap(-g0 * LOG2E));
                g1 = (0.125f * LOG2E) / (1.0f + ex2_ap(-g1 * LOG2E));
                __nv_bfloat162 p0 = __floats2bfloat162_rn(g0, mm.x * LOG2E);
                __nv_bfloat162 p1 = __floats2bfloat162_rn(g1, mm.y * LOG2E);
                *(uint2*)&gout[pidx] = make_uint2(*(unsigned*)&p0, *(unsigned*)&p1);
            }
        }
    } else {
        // ---------------- Q/K/V projection path ----------------
        const int pid = bid - GATE_BLKS;
        const int mt = pid / 12, combo = pid % 12;
        const int wsel = combo >> 2;
        const int m0 = mt * 64;
        const int n0 = (combo & 3) * 64;
        const float* bias = wsel == 0 ? bq : wsel == 1 ? bk : bv;

        gemm_bf16(g_xbf, g_wbf + (size_t)wsel * Hn * 128,
                  m0, n0, t, wm, gid, tig, As, Bs, c);

        const int r0 = m0 + wm + gid, r1 = r0 + 8;
        if (wsel < 2) {
            unsigned* out16 = wsel == 0 ? g_q16 : g_k16;
#pragma unroll
            for (int nt = 0; nt < 8; ++nt) {
                int cc = n0 + nt * 8 + 2 * tig;
                float2 bb = *(const float2*)&bias[cc];
                out16[(size_t)r0 * 128 + (cc >> 1)] = packbf(c[nt][0] + bb.x, c[nt][1] + bb.y);
                out16[(size_t)r1 * 128 + (cc >> 1)] = packbf(c[nt][2] + bb.x, c[nt][3] + bb.y);
            }
        } else {
            const int bb0 = r0 >> 9;
            const int tk0 = r0 & 511;
#pragma unroll
            for (int nt = 0; nt < 8; ++nt) {
                int cc = n0 + nt * 8 + 2 * tig;
                float2 bbv = *(const float2*)&bias[cc];
                int hh = cc >> 6, dl = cc & 63;
                size_t base = ((size_t)(bb0 * NHn + hh) * DHn + dl) * Ln + tk0;
                g_vt16[base]           = __float2bfloat16(c[nt][0] + bbv.x);
                g_vt16[base + Ln]      = __float2bfloat16(c[nt][1] + bbv.y);
                g_vt16[base + 8]       = __float2bfloat16(c[nt][2] + bbv.x);
                g_vt16[base + Ln + 8]  = __float2bfloat16(c[nt][3] + bbv.y);
            }
        }
    }
}

// ---------------- K2: fused attention (bf16, no-max softmax, HW ex2) ------
__global__ __launch_bounds__(128) void attn_mma()
{
    __shared__ unsigned Qs[64][36];
    __shared__ unsigned Ks[2][64][36];
    __shared__ unsigned Vp[2][64][36];
    __shared__ unsigned Gm[64][68];

    const int t = threadIdx.x;
    const int lane = t & 31, warp = t >> 5;
    const int gid = lane >> 2, tig = lane & 3;
    const int qt = blockIdx.x, h = blockIdx.y, b = blockIdx.z;
    const int q0 = qt * 64;
    const int wm = warp * 16;

    const unsigned* qptr = g_q16 + (size_t)b * Ln * 128 + h * 32;
    const unsigned* kptr = g_k16 + (size_t)b * Ln * 128 + h * 32;
    const unsigned* vtp = (const unsigned*)(g_vt16 + ((size_t)(b * NHn + h)) * DHn * Ln);
    const unsigned* gptr = g_gm + (size_t)b * Ln * Ln;

#pragma unroll
    for (int u = 0; u < 4; ++u) {
        int f = t + 128 * u;
        int row = f >> 3;
        int ch = (f & 7) * 4;
        *(uint4*)&Qs[row][ch] = *(const uint4*)&qptr[(size_t)(q0 + row) * 128 + ch];
    }

#pragma unroll
    for (int u = 0; u < 4; ++u) {
        int f = t + 128 * u;
        int row = f >> 3;
        int ch = (f & 7) * 4;
        cpa16(&Ks[0][row][ch], &kptr[(size_t)row * 128 + ch]);
        cpa16(&Vp[0][row][ch], &vtp[(size_t)row * 256 + ch]);
    }
    CP_COMMIT();
    __syncthreads();

    unsigned qf[4][4];
#pragma unroll
    for (int ks = 0; ks < 4; ++ks) {
        qf[ks][0] = Qs[wm + gid][ks * 8 + tig];
        qf[ks][1] = Qs[wm + gid + 8][ks * 8 + tig];
        qf[ks][2] = Qs[wm + gid][ks * 8 + 4 + tig];
        qf[ks][3] = Qs[wm + gid + 8][ks * 8 + 4 + tig];
    }

    float o[8][4] = {};
    float l_lo = 0.f, l_hi = 0.f;
    const int rl = q0 + wm + gid, rh = rl + 8;
    const int lrl = wm + gid, lrh = lrl + 8;

    for (int kb = 0; kb < 8; ++kb) {
        const int c0 = kb * 64;
        const int buf = kb & 1;

#pragma unroll
        for (int u = 0; u < 8; ++u) {
            int f = t + 128 * u;
            int row = f >> 4;
            int seg = (f & 15) * 4;
            cpa16(&Gm[row][seg], &gptr[(size_t)(q0 + row) * Ln + c0 + seg]);
        }
        CP_COMMIT();

        if (kb < 7) {
            const int c1 = c0 + 64;
            const int nb = buf ^ 1;
#pragma unroll
            for (int u = 0; u < 4; ++u) {
                int f = t + 128 * u;
                int row = f >> 3;
                int ch = (f & 7) * 4;
                cpa16(&Ks[nb][row][ch], &kptr[(size_t)(c1 + row) * 128 + ch]);
                cpa16(&Vp[nb][row][ch], &vtp[(size_t)row * 256 + (c1 >> 1) + ch]);
            }
            CP_COMMIT();
            CP_WAIT1();
        } else {
            CP_WAIT0();
        }
        __syncthreads();

        // S = Q @ K^T
        float s[8][4] = {};
#pragma unroll
        for (int ks = 0; ks < 4; ++ks) {
#pragma unroll
            for (int nt = 0; nt < 8; ++nt) {
                unsigned bfr[2];
                bfr[0] = Ks[buf][nt * 8 + gid][ks * 8 + tig];
                bfr[1] = Ks[buf][nt * 8 + gid][ks * 8 + 4 + tig];
                mma_bf16(s[nt], qf[ks], bfr);
            }
        }

        // p = ex2(s*gate' + mask')  — HW MUFU; logits bounded, no max needed
        float rs_lo = 0.f, rs_hi = 0.f;
#pragma unroll
        for (int nt = 0; nt < 8; ++nt) {
            int cl = nt * 8 + 2 * tig;
            uint2 pl = *(const uint2*)&Gm[lrl][cl];
            uint2 ph = *(const uint2*)&Gm[lrh][cl];
            float2 e0 = __bfloat1622float2(*(__nv_bfloat162*)&pl.x);
            float2 e1 = __bfloat1622float2(*(__nv_bfloat162*)&pl.y);
            float2 e2 = __bfloat1622float2(*(__nv_bfloat162*)&ph.x);
            float2 e3 = __bfloat1622float2(*(__nv_bfloat162*)&ph.y);
            s[nt][0] = ex2_ap(s[nt][0] * e0.x + e0.y);
            s[nt][1] = ex2_ap(s[nt][1] * e1.x + e1.y);
            s[nt][2] = ex2_ap(s[nt][2] * e2.x + e2.y);
            s[nt][3] = ex2_ap(s[nt][3] * e3.x + e3.y);
            rs_lo += s[nt][0] + s[nt][1];
            rs_hi += s[nt][2] + s[nt][3];
        }
        rs_lo += __shfl_xor_sync(0xffffffffu, rs_lo, 1);
        rs_lo += __shfl_xor_sync(0xffffffffu, rs_lo, 2);
        rs_hi += __shfl_xor_sync(0xffffffffu, rs_hi, 1);
        rs_hi += __shfl_xor_sync(0xffffffffu, rs_hi, 2);
        l_lo += rs_lo;
        l_hi += rs_hi;

        // O += P @ V
#pragma unroll
        for (int ks = 0; ks < 4; ++ks) {
            unsigned pa[4];
            pa[0] = packbf(s[2 * ks][0], s[2 * ks][1]);
            pa[1] = packbf(s[2 * ks][2], s[2 * ks][3]);
            pa[2] = packbf(s[2 * ks + 1][0], s[2 * ks + 1][1]);
            pa[3] = packbf(s[2 * ks + 1][2], s[2 * ks + 1][3]);
#pragma unroll
            for (int dt = 0; dt < 8; ++dt) {
                unsigned bfr[2];
                bfr[0] = Vp[buf][dt * 8 + gid][ks * 8 + tig];
                bfr[1] = Vp[buf][dt * 8 + gid][ks * 8 + 4 + tig];
                mma_bf16(o[dt], pa, bfr);
            }
        }
        __syncthreads();
    }

    float inv_lo = 1.0f / l_lo, inv_hi = 1.0f / l_hi;
    unsigned* cbase = g_ctx16 + (size_t)b * Ln * 128;
#pragma unroll
    for (int dt = 0; dt < 8; ++dt) {
        int pcol = h * 32 + dt * 4 + tig;
        cbase[(size_t)rl * 128 + pcol] = packbf(o[dt][0] * inv_lo, o[dt][1] * inv_lo);
        cbase[(size_t)rh * 128 + pcol] = packbf(o[dt][2] * inv_hi, o[dt][3] * inv_hi);
    }
}

// ---------------- K3: output projection + residual + layernorm ------------
__global__ __launch_bounds__(512) void outln_mma(
    const float* __restrict__ x, const float* __restrict__ bd,
    const float* __restrict__ lng, const float* __restrict__ lnb,
    float* __restrict__ out)
{
    extern __shared__ unsigned dsm[];
    unsigned* As = dsm;             // 2 * 64 * 36  = 4608
    unsigned* Bs = dsm + 4608;      // 2 * 256 * 36 = 18432
    __shared__ float redS[64][4];
    __shared__ float redQ[64][4];

    const int t = threadIdx.x;
    const int lane = t & 31, warp = t >> 5;
    const int gid = lane >> 2, tig = lane & 3;
    const int m0 = blockIdx.x * 64;
    const int mg = warp >> 2;
    const int nq = warp & 3;
    const int wm = mg * 16;
    const int wn = nq * 64;
    const unsigned* Wd = g_wbf + 4 * Hn * 128;

    float c[8][4] = {};

    {
        int row = t >> 3, ch = (t & 7) * 4;
        cpa16(&As[row * 36 + ch], &g_ctx16[(size_t)(m0 + row) * 128 + ch]);
#pragma unroll
        for (int u = 0; u < 4; ++u) {
            int f = t + 512 * u;
            int r2 = f >> 3, c2 = (f & 7) * 4;
            cpa16(&Bs[r2 * 36 + c2], &Wd[(size_t)r2 * 128 + c2]);
        }
        CP_COMMIT();
    }

    for (int i = 0; i < 4; ++i) {
        const int buf = i & 1;
        if (i < 3) {
            const int p1 = (i + 1) * 32;
            const int nb = buf ^ 1;
            int row = t >> 3, ch = (t & 7) * 4;
            cpa16(&As[nb * 2304 + row * 36 + ch], &g_ctx16[(size_t)(m0 + row) * 128 + p1 + ch]);
#pragma unroll
            for (int u = 0; u < 4; ++u) {
                int f = t + 512 * u;
                int r2 = f >> 3, c2 = (f & 7) * 4;
                cpa16(&Bs[nb * 9216 + r2 * 36 + c2], &Wd[(size_t)r2 * 128 + p1 + c2]);
            }
            CP_COMMIT();
            CP_WAIT1();
        } else {
            CP_WAIT0();
        }
        __syncthreads();
#pragma unroll
        for (int ks = 0; ks < 4; ++ks) {
            unsigned a[4];
            a[0] = As[buf * 2304 + (wm + gid) * 36 + ks * 8 + tig];
            a[1] = As[buf * 2304 + (wm + gid + 8) * 36 + ks * 8 + tig];
            a[2] = As[buf * 2304 + (wm + gid) * 36 + ks * 8 + 4 + tig];
            a[3] = As[buf * 2304 + (wm + gid + 8) * 36 + ks * 8 + 4 + tig];
#pragma unroll
            for (int nt = 0; nt < 8; ++nt) {
                unsigned bfr[2];
                bfr[0] = Bs[buf * 9216 + (wn + nt * 8 + gid) * 36 + ks * 8 + tig];
                bfr[1] = Bs[buf * 9216 + (wn + nt * 8 + gid) * 36 + ks * 8 + 4 + tig];
                mma_bf16(c[nt], a, bfr);
            }
        }
        __syncthreads();
    }

    const int lrl = wm + gid, lrh = lrl + 8;
    const size_t rl = m0 + lrl, rh = m0 + lrh;
    float s_lo = 0.f, s_hi = 0.f, q_lo = 0.f, q_hi = 0.f;
#pragma unroll
    for (int nt = 0; nt < 8; ++nt) {
        int cc = wn + nt * 8 + 2 * tig;
        float2 bb = *(const float2*)&bd[cc];
        float2 xl = *(const float2*)&x[rl * Hn + cc];
        float2 xh = *(const float2*)&x[rh * Hn + cc];
        c[nt][0] += bb.x + xl.x; c[nt][1] += bb.y + xl.y;
        c[nt][2] += bb.x + xh.x; c[nt][3] += bb.y + xh.y;
        s_lo += c[nt][0] + c[nt][1];
        s_hi += c[nt][2] + c[nt][3];
        q_lo += c[nt][0] * c[nt][0] + c[nt][1] * c[nt][1];
        q_hi += c[nt][2] * c[nt][2] + c[nt][3] * c[nt][3];
    }
    s_lo += __shfl_xor_sync(0xffffffffu, s_lo, 1);
    s_lo += __shfl_xor_sync(0xffffffffu, s_lo, 2);
    s_hi += __shfl_xor_sync(0xffffffffu, s_hi, 1);
    s_hi += __shfl_xor_sync(0xffffffffu, s_hi, 2);
    q_lo += __shfl_xor_sync(0xffffffffu, q_lo, 1);
    q_lo += __shfl_xor_sync(0xffffffffu, q_lo, 2);
    q_hi += __shfl_xor_sync(0xffffffffu, q_hi, 1);
    q_hi += __shfl_xor_sync(0xffffffffu, q_hi, 2);
    __syncthreads();
    if (tig == 0) {
        redS[lrl][nq] = s_lo; redQ[lrl][nq] = q_lo;
        redS[lrh][nq] = s_hi; redQ[lrh][nq] = q_hi;
    }
    __syncthreads();
    float mu_lo = (redS[lrl][0] + redS[lrl][1] + redS[lrl][2] + redS[lrl][3]) * (1.0f / Hn);
    float mu_hi = (redS[lrh][0] + redS[lrh][1] + redS[lrh][2] + redS[lrh][3]) * (1.0f / Hn);
    float ex_lo = (redQ[lrl][0] + redQ[lrl][1] + redQ[lrl][2] + redQ[lrl][3]) * (1.0f / Hn);
    float ex_hi = (redQ[lrh][0] + redQ[lrh][1] + redQ[lrh][2] + redQ[lrh][3]) * (1.0f / Hn);
    float iv_lo = rsqrtf(ex_lo - mu_lo * mu_lo + 1e-12f);
    float iv_hi = rsqrtf(ex_hi - mu_hi * mu_hi + 1e-12f);

#pragma unroll
    for (int nt = 0; nt < 8; ++nt) {
        int cc = wn + nt * 8 + 2 * tig;
        float2 g = *(const float2*)&lng[cc];
        float2 be = *(const float2*)&lnb[cc];
        *(float2*)&out[rl * Hn + cc] = make_float2(
            (c[nt][0] - mu_lo) * iv_lo * g.x + be.x,
            (c[nt][1] - mu_lo) * iv_lo * g.y + be.y);
        *(float2*)&out[rh * Hn + cc] = make_float2(
            (c[nt][2] - mu_hi) * iv_hi * g.x + be.x,
            (c[nt][3] - mu_hi) * iv_hi * g.y + be.y);
    }
}

// ---------------- K4: interval prediction head ---------------------------
__global__ __launch_bounds__(256) void pred_kernel(
    const float* __restrict__ hs, const int* __restrict__ slen,
    const float* __restrict__ Wt, const float* __restrict__ bt,
    float* __restrict__ out)
{
    __shared__ float red[256];
    const int b = blockIdx.x;
    const int t = threadIdx.x;
    const int len = slen[b];
    const float* e1 = hs + ((size_t)b * Ln + (len - 1)) * Hn;
    const float* e2 = hs + ((size_t)b * Ln + (len - 2)) * Hn;
    red[t] = Wt[t] * e1[t] + Wt[Hn + t] * e2[t];
    __syncthreads();
    for (int s = 128; s > 0; s >>= 1) {
        if (t < s) red[t] += red[t + s];
        __syncthreads();
    }
    if (t == 0) out[(size_t)Bn * Ln * Hn + b] = red[0] + bt[0];
}

// ---------------- launch --------------------------------------------------
extern "C" void kernel_launch(void* const* d_in, const int* in_sizes, int n_in,
                              void* d_out, int out_size)
{
    const float* x    = (const float*)d_in[0];
    const float* tseq = (const float*)d_in[1];
    const float* mask = (const float*)d_in[2];
    const int*   slen = (const int*)d_in[3];
    const float* Wq   = (const float*)d_in[4];
    const float* bq   = (const float*)d_in[5];
    const float* Wk   = (const float*)d_in[6];
    const float* bk   = (const float*)d_in[7];
    const float* Wv   = (const float*)d_in[8];
    const float* bv   = (const float*)d_in[9];
    const float* Wd   = (const float*)d_in[10];
    const float* bd   = (const float*)d_in[11];
    const float* lng  = (const float*)d_in[12];
    const float* lnb  = (const float*)d_in[13];
    const float* Wtq  = (const float*)d_in[14];
    const float* btq  = (const float*)d_in[15];
    const float* tw1  = (const float*)d_in[16];
    const float* tb1  = (const float*)d_in[17];
    const float* tow1 = (const float*)d_in[18];
    const float* tow2 = (const float*)d_in[19];
    const float* tob  = (const float*)d_in[20];
    const float* Wt   = (const float*)d_in[21];
    const float* bt   = (const float*)d_in[22];
    float* out = (float*)d_out;

    static const int OUTLN_SMEM = (4608 + 18432) * 4;  // 92160 B dynamic
    cudaFuncSetAttribute(outln_mma, cudaFuncAttributeMaxDynamicSharedMemorySize, OUTLN_SMEM);

    cvt_all<<<(NCVT + 255) / 256, 256>>>(
        (const float4*)x, (const float4*)Wq, (const float4*)Wk,
        (const float4*)Wv, (const float4*)Wtq, (const float4*)Wd,
        (const float4*)tw1, (const float4*)tb1,
        (const float4*)tow1, (const float4*)tow2);
    proj_tq<<<dim3(Bn * Ln / 64, 4), 128>>>(btq);
    fused_gate_qkv<<<GATE_BLKS + 3072, 128>>>(tseq, tob, mask, bq, bk, bv);
    attn_mma<<<dim3(Ln / 64, NHn, Bn), 128>>>();
    outln_mma<<<dim3(Bn * Ln / 64), 512, OUTLN_SMEM>>>(x, bd, lng, lnb, out);
    pred_kernel<<<dim3(Bn), 256>>>(out, slen, Wt, bt, out);
}